// round 3
// baseline (speedup 1.0000x reference)
#include <cuda_runtime.h>
#include <math.h>
#include <stddef.h>

// Problem constants
#define MV   128      // sequence length M
#define BV   32       // batch
#define HV   256      // hidden == embed dim
#define VV   4000     // vocab
#define SV   126      // M-2 segment starts
#define NBV  4032     // S*B decoder batch
#define LV   4
#define NROW 20160    // 5 * NBV logits rows
#define NCB  63       // ceil(4000/64) column blocks in logits GEMM
#define NEGBIG (-1e6f)

// ---------------- device scratch (static globals; no allocations) ----------------
__device__ float g_inp[4096*256];       // embedded inputs, row = m*32+b
__device__ float g_issingle[4096];      // -1e6 if token in {0,1,2}, row m*32+b
__device__ float g_xge[4096*1024];      // encoder input-gate precompute (incl. both biases)
__device__ float g_xgd[4160*1024];      // decoder input-gate precompute, 130 positions x 32
__device__ float g_henc[2*8192];        // encoder h, [buf][b*256+k], double buffered
__device__ float g_cenc[8192];          // encoder c
__device__ float g_encout[4096*256];    // 0.5*h, row m*32+b
__device__ float g_sos[4032*256];
__device__ float g_sosxg[4032*1024];    // sos @ dec_Wih^T + biases
__device__ float g_dech[4032*256];
__device__ float g_decc[4032*256];
__device__ float g_gh[4032*1024];       // decoder recurrent gates
__device__ float g_decout[5*4032*256];  // decoder hidden states, [t][s*32+b][h]
__device__ float g_pmax[NROW*NCB];
__device__ float g_psum[NROW*NCB];
__device__ float g_logZ[NROW];
__device__ float g_lt[16128];           // logits at target token, id=(s*4+k)*32+b
__device__ float g_le[16128];           // logits at EOS (time k+1)
__device__ float g_logpy[16128];        // segment log-probs

__device__ __forceinline__ float sigm(float x){ return 1.f/(1.f + expf(-x)); }

// ---------------- embedding gather + is_single ----------------
__global__ void embed_kernel(const int* __restrict__ x, const float* __restrict__ emb){
    int blk = blockIdx.x;            // m*32+b
    int m = blk >> 5, b = blk & 31;
    int token = x[b*MV + m];
    g_inp[(size_t)blk*256 + threadIdx.x] = emb[(size_t)token*256 + threadIdx.x];
    if (threadIdx.x == 0)
        g_issingle[blk] = ((unsigned)token <= 2u) ? NEGBIG : 0.f;
}

// ---------------- init encoder state, decoder pad-row gates ----------------
__global__ void init_state(const float* __restrict__ h0, const float* __restrict__ c0,
                           const float* __restrict__ dbih, const float* __restrict__ dbhh){
    int idx = blockIdx.x*256 + threadIdx.x;   // 320*256 = 81920
    if (idx < 8192) {
        g_henc[idx] = h0[idx & 255];
    } else if (idx < 16384) {
        g_cenc[idx - 8192] = c0[idx & 255];
    } else if (idx < 16384 + 65536) {
        int j = idx - 16384;                  // pad positions 128,129 (zero input -> bih+bhh)
        int n = j & 1023;
        g_xgd[(size_t)4096*1024 + j] = dbih[n] + dbhh[n];
    }
}

// ---------------- generic fp32 GEMM: C[R][N] = A[R][256] @ W[N][256]^T + b0 + b1 ----
__global__ void sgemm_nt(const float* __restrict__ A, const float* __restrict__ W,
                         const float* __restrict__ b0, const float* __restrict__ b1,
                         float* __restrict__ C, int R, int N, int act){
    __shared__ float As[16][128];
    __shared__ float Bs[16][68];
    int tid = threadIdx.x;
    int r0 = blockIdx.x*128, n0 = blockIdx.y*64;
    int ty = tid >> 4, tx = tid & 15;
    float acc[8][4];
    #pragma unroll
    for (int i=0;i<8;i++)
        #pragma unroll
        for (int j=0;j<4;j++) acc[i][j] = 0.f;

    for (int kk=0; kk<256; kk+=16){
        int row = tid >> 2, kq = (tid & 3)*4;
        #pragma unroll
        for (int i=0;i<2;i++){
            int rr = row + i*64;
            int ra = min(r0 + rr, R-1);
            float4 v = *(const float4*)&A[(size_t)ra*256 + kk + kq];
            As[kq+0][rr]=v.x; As[kq+1][rr]=v.y; As[kq+2][rr]=v.z; As[kq+3][rr]=v.w;
        }
        {
            int na = min(n0 + row, N-1);
            float4 w = *(const float4*)&W[(size_t)na*256 + kk + kq];
            Bs[kq+0][row]=w.x; Bs[kq+1][row]=w.y; Bs[kq+2][row]=w.z; Bs[kq+3][row]=w.w;
        }
        __syncthreads();
        #pragma unroll
        for (int k=0;k<16;k++){
            float a[8], bb[4];
            #pragma unroll
            for (int i=0;i<8;i++) a[i] = As[k][ty*8+i];
            #pragma unroll
            for (int j=0;j<4;j++) bb[j] = Bs[k][tx*4+j];
            #pragma unroll
            for (int i=0;i<8;i++)
                #pragma unroll
                for (int j=0;j<4;j++) acc[i][j] = fmaf(a[i], bb[j], acc[i][j]);
        }
        __syncthreads();
    }
    #pragma unroll
    for (int i=0;i<8;i++){
        int r = r0 + ty*8 + i;
        if (r >= R) continue;
        #pragma unroll
        for (int j=0;j<4;j++){
            int n = n0 + tx*4 + j;
            if (n >= N) continue;
            float v = acc[i][j];
            if (b0) v += b0[n];
            if (b1) v += b1[n];
            if (act) v = tanhf(v);
            C[(size_t)r*N + n] = v;
        }
    }
}

// ---------------- logits GEMM with fused per-block (max, sumexp) partials ----------
__global__ void sgemm_logits(const float* __restrict__ A, const float* __restrict__ W,
                             const float* __restrict__ bias){
    __shared__ float As[16][128];
    __shared__ float Bs[16][68];
    int tid = threadIdx.x;
    int r0 = blockIdx.x*128, n0 = blockIdx.y*64;
    int cb = blockIdx.y;
    int ty = tid >> 4, tx = tid & 15;
    float acc[8][4];
    #pragma unroll
    for (int i=0;i<8;i++)
        #pragma unroll
        for (int j=0;j<4;j++) acc[i][j] = 0.f;

    for (int kk=0; kk<256; kk+=16){
        int row = tid >> 2, kq = (tid & 3)*4;
        #pragma unroll
        for (int i=0;i<2;i++){
            int rr = row + i*64;
            int ra = min(r0 + rr, NROW-1);
            float4 v = *(const float4*)&A[(size_t)ra*256 + kk + kq];
            As[kq+0][rr]=v.x; As[kq+1][rr]=v.y; As[kq+2][rr]=v.z; As[kq+3][rr]=v.w;
        }
        {
            int na = min(n0 + row, VV-1);
            float4 w = *(const float4*)&W[(size_t)na*256 + kk + kq];
            Bs[kq+0][row]=w.x; Bs[kq+1][row]=w.y; Bs[kq+2][row]=w.z; Bs[kq+3][row]=w.w;
        }
        __syncthreads();
        #pragma unroll
        for (int k=0;k<16;k++){
            float a[8], bb[4];
            #pragma unroll
            for (int i=0;i<8;i++) a[i] = As[k][ty*8+i];
            #pragma unroll
            for (int j=0;j<4;j++) bb[j] = Bs[k][tx*4+j];
            #pragma unroll
            for (int i=0;i<8;i++)
                #pragma unroll
                for (int j=0;j<4;j++) acc[i][j] = fmaf(a[i], bb[j], acc[i][j]);
        }
        __syncthreads();
    }
    // epilogue: per-row max + sumexp across the 64 cols of this block
    float bv[4];
    #pragma unroll
    for (int j=0;j<4;j++){
        int n = n0 + tx*4 + j;
        bv[j] = (n < VV) ? bias[n] : 0.f;
    }
    #pragma unroll
    for (int i=0;i<8;i++){
        float vv[4];
        float m = -1e30f;
        #pragma unroll
        for (int j=0;j<4;j++){
            int n = n0 + tx*4 + j;
            vv[j] = (n < VV) ? (acc[i][j] + bv[j]) : -1e30f;
            m = fmaxf(m, vv[j]);
        }
        #pragma unroll
        for (int s=1;s<16;s<<=1) m = fmaxf(m, __shfl_xor_sync(0xffffffffu, m, s));
        float ssum = 0.f;
        #pragma unroll
        for (int j=0;j<4;j++) ssum += __expf(vv[j] - m);
        #pragma unroll
        for (int s=1;s<16;s<<=1) ssum += __shfl_xor_sync(0xffffffffu, ssum, s);
        int r = r0 + ty*8 + i;
        if (tx == 0 && r < NROW){
            g_pmax[(size_t)r*NCB + cb] = m;
            g_psum[(size_t)r*NCB + cb] = ssum;
        }
    }
}

__global__ void reduce_logz(){
    int row = blockIdx.x*8 + (threadIdx.x >> 5);
    int lane = threadIdx.x & 31;
    if (row >= NROW) return;
    float m1 = -1e30f, s1 = 0.f, m2 = -1e30f, s2 = 0.f;
    if (lane < NCB){ m1 = g_pmax[(size_t)row*NCB + lane]; s1 = g_psum[(size_t)row*NCB + lane]; }
    if (lane + 32 < NCB){ m2 = g_pmax[(size_t)row*NCB + lane + 32]; s2 = g_psum[(size_t)row*NCB + lane + 32]; }
    float m = fmaxf(m1, m2);
    #pragma unroll
    for (int s=16;s;s>>=1) m = fmaxf(m, __shfl_xor_sync(0xffffffffu, m, s));
    float ss = s1*__expf(m1 - m) + s2*__expf(m2 - m);
    #pragma unroll
    for (int s=16;s;s>>=1) ss += __shfl_xor_sync(0xffffffffu, ss, s);
    if (lane == 0) g_logZ[row] = m + logf(ss);
}

// ---------------- encoder LSTM step (fused gates GEMM + pointwise) ----------------
__global__ void enc_step(int t, const float* __restrict__ Whh){
    __shared__ float hs[128][32];
    __shared__ float ws[32][128];
    int tid = threadIdx.x;
    int hcl = tid >> 5, b = tid & 31;
    int hc0 = blockIdx.x * 8;
    int hc = hc0 + hcl;
    const float* hprev = g_henc + (size_t)(t & 1) * 8192;
    float ai=0.f, af=0.f, ag=0.f, ao=0.f;
    for (int h0=0; h0<256; h0+=128){
        #pragma unroll
        for (int i=0;i<4;i++){
            int q = tid + i*256;
            int bb = q >> 5; int kk = (q & 31)*4;
            float4 v = *(const float4*)&hprev[bb*256 + h0 + kk];
            hs[kk+0][bb]=v.x; hs[kk+1][bb]=v.y; hs[kk+2][bb]=v.z; hs[kk+3][bb]=v.w;
        }
        #pragma unroll
        for (int i=0;i<4;i++){
            int q = tid + i*256;
            int li = q >> 5; int kq = (q & 31)*4;
            int row = (li >> 3)*256 + hc0 + (li & 7);
            *(float4*)&ws[li][kq] = *(const float4*)&Whh[(size_t)row*256 + h0 + kq];
        }
        __syncthreads();
        #pragma unroll 8
        for (int k=0;k<128;k+=4){
            float4 wi = *(const float4*)&ws[hcl     ][k];
            float4 wf = *(const float4*)&ws[8  + hcl][k];
            float4 wg = *(const float4*)&ws[16 + hcl][k];
            float4 wo = *(const float4*)&ws[24 + hcl][k];
            float h0v = hs[k][b], h1v = hs[k+1][b], h2v = hs[k+2][b], h3v = hs[k+3][b];
            ai = fmaf(wi.x,h0v, fmaf(wi.y,h1v, fmaf(wi.z,h2v, fmaf(wi.w,h3v, ai))));
            af = fmaf(wf.x,h0v, fmaf(wf.y,h1v, fmaf(wf.z,h2v, fmaf(wf.w,h3v, af))));
            ag = fmaf(wg.x,h0v, fmaf(wg.y,h1v, fmaf(wg.z,h2v, fmaf(wg.w,h3v, ag))));
            ao = fmaf(wo.x,h0v, fmaf(wo.y,h1v, fmaf(wo.z,h2v, fmaf(wo.w,h3v, ao))));
        }
        __syncthreads();
    }
    const float* xg = g_xge + (size_t)(t*32 + b)*1024;
    ai += xg[hc]; af += xg[256+hc]; ag += xg[512+hc]; ao += xg[768+hc];
    int rb = b*256 + hc;
    float cv = g_cenc[rb];
    cv = sigm(af)*cv + sigm(ai)*tanhf(ag);
    g_cenc[rb] = cv;
    float hv = sigm(ao)*tanhf(cv);
    g_henc[(size_t)((t+1)&1)*8192 + rb] = hv;
    g_encout[(size_t)(t*32 + b)*256 + hc] = 0.5f*hv;
}

// ---------------- decoder pointwise update ----------------
__global__ void dec_update(int t){
    int idx = blockIdx.x*256 + threadIdx.x;   // 4032*256
    int r = idx >> 8; int hc = idx & 255;
    int s = r >> 5; int b = r & 31;
    const float* xg = (t == 0) ? &g_sosxg[(size_t)r*1024]
                               : &g_xgd[((size_t)(s + t)*32 + b)*1024];
    const float* g = &g_gh[(size_t)r*1024];
    float gi = g[hc]       + xg[hc];
    float gf = g[256 + hc] + xg[256 + hc];
    float gg = g[512 + hc] + xg[512 + hc];
    float go = g[768 + hc] + xg[768 + hc];
    float cv = (t == 0) ? 0.f : g_decc[idx];
    cv = sigm(gf)*cv + sigm(gi)*tanhf(gg);
    g_decc[idx] = cv;
    float hv = sigm(go)*tanhf(cv);
    g_dech[idx] = hv;
    g_decout[(size_t)t*4032*256 + idx] = hv;
}

// ---------------- target / EOS logits (warp-per-dot) ----------------
__global__ void dots_kernel(const int* __restrict__ x, const float* __restrict__ emb,
                            const float* __restrict__ e2vb){
    int item = blockIdx.x*8 + (threadIdx.x >> 5);   // 0..32255
    int lane = threadIdx.x & 31;
    bool iseos = item >= 16128;
    int id = iseos ? item - 16128 : item;
    int s = id >> 7; int rem = id & 127; int k = rem >> 5; int b = rem & 31;
    int t = iseos ? (k + 1) : k;
    int token;
    if (iseos) token = 3;
    else { int pos = s + 1 + k; token = (pos < MV) ? x[b*MV + pos] : 0; }
    const float* a = g_decout + ((size_t)t*4032 + s*32 + b)*256;
    const float* w = emb + (size_t)token*256;
    int base = lane*8;
    float4 a1 = *(const float4*)&a[base], a2 = *(const float4*)&a[base+4];
    float4 w1 = *(const float4*)&w[base], w2 = *(const float4*)&w[base+4];
    float sum = a1.x*w1.x + a1.y*w1.y + a1.z*w1.z + a1.w*w1.w
              + a2.x*w2.x + a2.y*w2.y + a2.z*w2.z + a2.w*w2.w;
    #pragma unroll
    for (int sft=16; sft; sft>>=1) sum += __shfl_xor_sync(0xffffffffu, sum, sft);
    if (lane == 0){
        float v = sum + e2vb[token];
        if (iseos) g_le[id] = v; else g_lt[id] = v;
    }
}

// ---------------- build per-segment log-probs ----------------
__global__ void build_logpy(){
    int s = blockIdx.x, b = threadIdx.x;  // 126 x 32
    float cum = 0.f;
    float isstart = g_issingle[(s+1)*32 + b];
    for (int k=0;k<4;k++){
        int id = (s*4 + k)*32 + b;
        float tlp = g_lt[id] - g_logZ[k*4032 + s*32 + b];
        int pos = s + 1 + k;
        float segis = (pos < MV) ? g_issingle[pos*32 + b] : 0.f;
        cum += tlp + ((k >= 1) ? segis : 0.f);
        float v = cum + ((k >= 1) ? isstart : 0.f)
                + (g_le[id] - g_logZ[(k+1)*4032 + s*32 + b]);
        bool valid = (s + 1 + k) <= 126;
        g_logpy[id] = valid ? v : NEGBIG;
    }
}

// ---------------- segmental DP + final reduction ----------------
__global__ void dp_final(const int* __restrict__ lengths, float* __restrict__ out){
    int b = threadIdx.x;  // 32 threads
    float ap0 = 0.f, ap1 = NEGBIG, ap2 = NEGBIG, ap3 = NEGBIG;
    int target = lengths[b] - 2;
    float nll = 0.f;   // alphas[0] = 0
    for (int e=1; e<=126; e++){
        float t0 = ap0 + g_logpy[((e-1)*4 + 0)*32 + b];
        float t1 = (e >= 2) ? ap1 + g_logpy[((e-2)*4 + 1)*32 + b] : -1e30f;
        float t2 = (e >= 3) ? ap2 + g_logpy[((e-3)*4 + 2)*32 + b] : -1e30f;
        float t3 = (e >= 4) ? ap3 + g_logpy[((e-4)*4 + 3)*32 + b] : -1e30f;
        float m = fmaxf(fmaxf(t0,t1), fmaxf(t2,t3));
        float ss = expf(t0-m) + expf(t1-m) + expf(t2-m) + expf(t3-m);
        float ae = m + logf(ss);
        ap3 = ap2; ap2 = ap1; ap1 = ap0; ap0 = ae;
        if (e == target) nll = -ae;
    }
    float sumn = nll;
    int sl = lengths[b];
    #pragma unroll
    for (int sft=16; sft; sft>>=1){
        sumn += __shfl_xor_sync(0xffffffffu, sumn, sft);
        sl   += __shfl_xor_sync(0xffffffffu, sl, sft);
    }
    if (b == 0) out[0] = sumn / (float)(sl - 2*BV);
}

// ---------------- host launcher ----------------
extern "C" void kernel_launch(void* const* d_in, const int* in_sizes, int n_in,
                              void* d_out, int out_size){
    const int*   x     = (const int*)d_in[0];
    const int*   lens  = (const int*)d_in[1];
    const float* emb   = (const float*)d_in[2];
    const float* e2vb  = (const float*)d_in[3];
    const float* eWih  = (const float*)d_in[4];
    const float* eWhh  = (const float*)d_in[5];
    const float* ebih  = (const float*)d_in[6];
    const float* ebhh  = (const float*)d_in[7];
    const float* eh0   = (const float*)d_in[8];
    const float* ec0   = (const float*)d_in[9];
    const float* dWih  = (const float*)d_in[10];
    const float* dWhh  = (const float*)d_in[11];
    const float* dbih  = (const float*)d_in[12];
    const float* dbhh  = (const float*)d_in[13];
    const float* dhtW  = (const float*)d_in[14];
    const float* dhtb  = (const float*)d_in[15];
    const float* sosW  = (const float*)d_in[16];
    const float* sosb  = (const float*)d_in[17];
    float* out = (float*)d_out;

    float *inp, *xge, *xgd, *encout, *sos, *sosxg, *dech, *gh, *decout;
    cudaGetSymbolAddress((void**)&inp,    g_inp);
    cudaGetSymbolAddress((void**)&xge,    g_xge);
    cudaGetSymbolAddress((void**)&xgd,    g_xgd);
    cudaGetSymbolAddress((void**)&encout, g_encout);
    cudaGetSymbolAddress((void**)&sos,    g_sos);
    cudaGetSymbolAddress((void**)&sosxg,  g_sosxg);
    cudaGetSymbolAddress((void**)&dech,   g_dech);
    cudaGetSymbolAddress((void**)&gh,     g_gh);
    cudaGetSymbolAddress((void**)&decout, g_decout);

    embed_kernel<<<4096, 256>>>(x, emb);
    init_state<<<320, 256>>>(eh0, ec0, dbih, dbhh);

    // input-gate precomputes (include both biases)
    sgemm_nt<<<dim3(32,16), 256>>>(inp, eWih, ebih, ebhh, xge, 4096, 1024, 0);
    sgemm_nt<<<dim3(32,16), 256>>>(inp, dWih, dbih, dbhh, xgd, 4096, 1024, 0);

    // encoder recurrence
    for (int t=0; t<MV; t++)
        enc_step<<<32, 256>>>(t, eWhh);

    // sos / dec_h0 / sos input-gates
    sgemm_nt<<<dim3(32,4),  256>>>(encout, sosW, sosb, nullptr, sos,   NBV, 256, 0);
    sgemm_nt<<<dim3(32,4),  256>>>(encout, dhtW, dhtb, nullptr, dech,  NBV, 256, 1);
    sgemm_nt<<<dim3(32,16), 256>>>(sos,    dWih, dbih, dbhh,    sosxg, NBV, 1024, 0);

    // decoder recurrence (5 steps)
    for (int t=0; t<5; t++){
        sgemm_nt<<<dim3(32,16), 256>>>(dech, dWhh, nullptr, nullptr, gh, NBV, 1024, 0);
        dec_update<<<4032, 256>>>(t);
    }

    // fused logits logsumexp
    sgemm_logits<<<dim3(158, NCB), 256>>>(decout, emb, e2vb);
    reduce_logz<<<2520, 256>>>();
    dots_kernel<<<4032, 256>>>(x, emb, e2vb);
    build_logpy<<<126, 32>>>();
    dp_final<<<1, 32>>>(lens, out);
}